// round 1
// baseline (speedup 1.0000x reference)
#include <cuda_runtime.h>
#include <math.h>

#define BATCH 4096
#define NCLS 1000
#define DIM 512
#define QSZ 8192
#define INV_T (1.0f / 0.07f)
#define EPSP 1e-8f

// ---------------- scratch (__device__ globals; no allocations allowed) ------
__device__ float g_feat[BATCH * DIM];           // normalized embeddings      8 MB
__device__ float g_cent[NCLS * DIM];            // normalized centers         2 MB
__device__ float g_qp[QSZ * DIM];               // label-permuted queue      16 MB
__device__ float g_S[(size_t)BATCH * QSZ];      // feat @ queue_p^T / T     128 MB
__device__ float g_CS[(size_t)BATCH * NCLS];    // feat @ cent^T / T         16 MB
__device__ int   g_start[NCLS + 2];             // segment starts per class
__device__ int   g_perm[QSZ];                   // permutation (sorted by label)
__device__ double g_acc[2];                     // [0]=cls nll sum, [1]=contrastive nll sum

// ---------------- row L2 normalize (block per row, 128 threads) -------------
__global__ void norm_rows(const float* __restrict__ x, float* __restrict__ y) {
    int r = blockIdx.x;
    const float4* xr = (const float4*)(x + (size_t)r * DIM);
    float4 v = xr[threadIdx.x];
    float ss = v.x * v.x + v.y * v.y + v.z * v.z + v.w * v.w;
#pragma unroll
    for (int o = 16; o; o >>= 1) ss += __shfl_down_sync(0xffffffffu, ss, o);
    __shared__ float sh[4];
    if ((threadIdx.x & 31) == 0) sh[threadIdx.x >> 5] = ss;
    __syncthreads();
    float tot = sh[0] + sh[1] + sh[2] + sh[3];
    float inv = 1.0f / fmaxf(sqrtf(tot), 1e-12f);
    float4 o4 = make_float4(v.x * inv, v.y * inv, v.z * inv, v.w * inv);
    ((float4*)(y + (size_t)r * DIM))[threadIdx.x] = o4;
}

// ---------------- counting sort of queue labels (single block) --------------
__global__ void build_perm(const int* __restrict__ labels) {
    __shared__ int cnt[NCLS + 1];
    __shared__ int cur[NCLS + 1];
    int tid = threadIdx.x;
    for (int i = tid; i < NCLS + 1; i += blockDim.x) cnt[i] = 0;
    if (tid == 0) { g_acc[0] = 0.0; g_acc[1] = 0.0; }
    __syncthreads();
    for (int q = tid; q < QSZ; q += blockDim.x) {
        int l = labels[q];
        int b = (l >= 0 && l < NCLS) ? l : NCLS;
        atomicAdd(&cnt[b], 1);
    }
    __syncthreads();
    if (tid == 0) {
        int run = 0;
        for (int c = 0; c < NCLS + 1; c++) {
            cur[c] = run;
            g_start[c] = run;
            run += cnt[c];
        }
        g_start[NCLS + 1] = run;
    }
    __syncthreads();
    for (int q = tid; q < QSZ; q += blockDim.x) {
        int l = labels[q];
        int b = (l >= 0 && l < NCLS) ? l : NCLS;
        int p = atomicAdd(&cur[b], 1);
        g_perm[p] = q;
    }
}

// ---------------- gather queue rows into label-sorted order -----------------
__global__ void permute_queue(const float* __restrict__ queue) {
    int idx = blockIdx.x * blockDim.x + threadIdx.x;  // QSZ * 128 threads
    int r = idx >> 7, c = idx & 127;
    int src = g_perm[r];
    ((float4*)g_qp)[(size_t)r * 128 + c] =
        ((const float4*)queue)[(size_t)src * 128 + c];
}

// ---------------- SGEMM: C[m,n] = alpha * sum_k A[m,k]*B[n,k] ---------------
// A: [M,K] row-major, Bm: [N,K] row-major, C: [M,N] row-major. M%128==0, K%8==0.
#define GBM 128
#define GBN 128
#define GBK 8
#define GTM 8
#define GTN 8
__global__ __launch_bounds__(256) void gemm_nt(const float* __restrict__ A,
                                               const float* __restrict__ Bm,
                                               float* __restrict__ Cm,
                                               int N, int K, float alpha) {
    __shared__ float As[GBK][GBM];
    __shared__ float Bs[GBK][GBN];
    int bx = blockIdx.x;  // N tile
    int by = blockIdx.y;  // M tile
    int tid = threadIdx.x;
    int lr = tid >> 1;            // 0..127 : row within tile for loading
    int lc = (tid & 1) * 4;       // 0 or 4 : k offset for float4 load
    int trow = (tid >> 4) * GTM;  // 0..120
    int tcol = (tid & 15) * GTN;  // 0..120

    float acc[GTM][GTN] = {};
    const float* Ap = A + (size_t)(by * GBM + lr) * K + lc;
    const float* Bp = Bm + (size_t)(bx * GBN + lr) * K + lc;
    bool bvalid = (bx * GBN + lr) < N;

    for (int k0 = 0; k0 < K; k0 += GBK) {
        float4 av = *(const float4*)(Ap + k0);
        As[lc + 0][lr] = av.x; As[lc + 1][lr] = av.y;
        As[lc + 2][lr] = av.z; As[lc + 3][lr] = av.w;
        float4 bv = make_float4(0.f, 0.f, 0.f, 0.f);
        if (bvalid) bv = *(const float4*)(Bp + k0);
        Bs[lc + 0][lr] = bv.x; Bs[lc + 1][lr] = bv.y;
        Bs[lc + 2][lr] = bv.z; Bs[lc + 3][lr] = bv.w;
        __syncthreads();
#pragma unroll
        for (int k = 0; k < GBK; k++) {
            float ar[GTM], br[GTN];
#pragma unroll
            for (int i = 0; i < GTM; i++) ar[i] = As[k][trow + i];
#pragma unroll
            for (int j = 0; j < GTN; j++) br[j] = Bs[k][tcol + j];
#pragma unroll
            for (int i = 0; i < GTM; i++)
#pragma unroll
                for (int j = 0; j < GTN; j++) acc[i][j] = fmaf(ar[i], br[j], acc[i][j]);
        }
        __syncthreads();
    }
#pragma unroll
    for (int i = 0; i < GTM; i++) {
        int gm = by * GBM + trow + i;
#pragma unroll
        for (int j = 0; j < GTN; j++) {
            int gn = bx * GBN + tcol + j;
            if (gn < N) Cm[(size_t)gm * N + gn] = alpha * acc[i][j];
        }
    }
}

// ---------------- contrastive CE: one block per batch row -------------------
__global__ __launch_bounds__(256) void row_contrastive(const float* __restrict__ prior,
                                                       const int* __restrict__ targets,
                                                       const unsigned char* __restrict__ init) {
    int b = blockIdx.x, tid = threadIdx.x;
    const float* Srow = g_S + (size_t)b * QSZ;
    const float* CSrow = g_CS + (size_t)b * NCLS;
    int tgt = targets[b];
    __shared__ float sm[256], ssum[256];
    __shared__ float stv;
    float m = -INFINITY, s = 0.f;
    for (int c = tid; c < NCLS; c += 256) {
        int s0 = g_start[c], s1 = g_start[c + 1];
        int cnt = s1 - s0;
        float ql = 0.f;
        if (cnt > 0) {
            float mx = -INFINITY;
            for (int q = s0; q < s1; q++) mx = fmaxf(mx, Srow[q]);
            float se = 0.f;
            for (int q = s0; q < s1; q++) se += __expf(Srow[q] - mx);
            ql = mx + __logf(se) - __logf((float)cnt);
        }
        float cl = init[c] ? CSrow[c] : 0.f;
        float a = fmaxf(cl, ql), d = fminf(cl, ql);
        float comp = a + log1pf(__expf(d - a));            // logaddexp
        float v = comp - logf(fmaxf(prior[c], EPSP));      // - prior_adjust
        if (c == tgt) stv = v;
        if (v > m) { s = s * __expf(m - v) + 1.f; m = v; }
        else        { s += __expf(v - m); }
    }
    sm[tid] = m; ssum[tid] = s;
    __syncthreads();
    for (int o = 128; o; o >>= 1) {
        if (tid < o) {
            float m2 = sm[tid + o], s2 = ssum[tid + o];
            float M = fmaxf(sm[tid], m2);
            ssum[tid] = ssum[tid] * __expf(sm[tid] - M) + s2 * __expf(m2 - M);
            sm[tid] = M;
        }
        __syncthreads();
    }
    if (tid == 0) {
        float lse = sm[0] + __logf(ssum[0]);
        atomicAdd(&g_acc[1], (double)(lse - stv));
    }
}

// ---------------- plain classification CE: one block per batch row ----------
__global__ __launch_bounds__(256) void row_cls(const float* __restrict__ logits,
                                               const float* __restrict__ prior,
                                               const int* __restrict__ targets) {
    int b = blockIdx.x, tid = threadIdx.x;
    const float* L = logits + (size_t)b * NCLS;
    int tgt = targets[b];
    __shared__ float sm[256], ssum[256];
    __shared__ float stv;
    float m = -INFINITY, s = 0.f;
    for (int c = tid; c < NCLS; c += 256) {
        float v = L[c] - logf(fmaxf(prior[c], EPSP));
        if (c == tgt) stv = v;
        if (v > m) { s = s * __expf(m - v) + 1.f; m = v; }
        else        { s += __expf(v - m); }
    }
    sm[tid] = m; ssum[tid] = s;
    __syncthreads();
    for (int o = 128; o; o >>= 1) {
        if (tid < o) {
            float m2 = sm[tid + o], s2 = ssum[tid + o];
            float M = fmaxf(sm[tid], m2);
            ssum[tid] = ssum[tid] * __expf(sm[tid] - M) + s2 * __expf(m2 - M);
            sm[tid] = M;
        }
        __syncthreads();
    }
    if (tid == 0) {
        float lse = sm[0] + __logf(ssum[0]);
        atomicAdd(&g_acc[0], (double)(lse - stv));
    }
}

__global__ void finalize(float* out) {
    out[0] = (float)(1.0 * (g_acc[0] / BATCH) + 0.1 * (g_acc[1] / BATCH));
}

// ---------------- launch ----------------------------------------------------
extern "C" void kernel_launch(void* const* d_in, const int* in_sizes, int n_in,
                              void* d_out, int out_size) {
    const float* logits    = (const float*)d_in[0];          // [4096,1000]
    const float* embed     = (const float*)d_in[1];          // [4096,512]
    const float* centers   = (const float*)d_in[2];          // [1000,512]
    const float* queue     = (const float*)d_in[3];          // [8192,512]
    const float* prior     = (const float*)d_in[4];          // [1000]
    const int*   targets   = (const int*)d_in[5];            // [4096]
    const unsigned char* cinit = (const unsigned char*)d_in[6]; // [1000] bool
    const int*   qlabels   = (const int*)d_in[7];            // [8192]
    float* out = (float*)d_out;

    float* feat; cudaGetSymbolAddress((void**)&feat, g_feat);
    float* cent; cudaGetSymbolAddress((void**)&cent, g_cent);
    float* qp;   cudaGetSymbolAddress((void**)&qp,   g_qp);
    float* S;    cudaGetSymbolAddress((void**)&S,    g_S);
    float* CS;   cudaGetSymbolAddress((void**)&CS,   g_CS);

    norm_rows<<<BATCH, 128>>>(embed, feat);
    norm_rows<<<NCLS, 128>>>(centers, cent);
    build_perm<<<1, 1024>>>(qlabels);
    permute_queue<<<(QSZ * 128) / 256, 256>>>(queue);

    dim3 gS(QSZ / GBN, BATCH / GBM);
    gemm_nt<<<gS, 256>>>(feat, qp, S, QSZ, DIM, INV_T);
    dim3 gC((NCLS + GBN - 1) / GBN, BATCH / GBM);
    gemm_nt<<<gC, 256>>>(feat, cent, CS, NCLS, DIM, INV_T);

    row_contrastive<<<BATCH, 256>>>(prior, targets, cinit);
    row_cls<<<BATCH, 256>>>(logits, prior, targets);
    finalize<<<1, 1>>>(out);
}

// round 2
// speedup vs baseline: 1.0037x; 1.0037x over previous
#include <cuda_runtime.h>
#include <math.h>

#define BATCH 4096
#define NCLS 1000
#define DIM 512
#define QSZ 8192
#define INV_T (1.0f / 0.07f)
#define EPSP 1e-8f

// ---------------- scratch (__device__ globals; no allocations allowed) ------
__device__ float g_feat[BATCH * DIM];           // normalized embeddings      8 MB
__device__ float g_cent[NCLS * DIM];            // normalized centers         2 MB
__device__ float g_qp[QSZ * DIM];               // label-permuted queue      16 MB
__device__ float g_S[(size_t)BATCH * QSZ];      // feat @ queue_p^T / T     128 MB
__device__ float g_CS[(size_t)BATCH * NCLS];    // feat @ cent^T / T         16 MB
__device__ int   g_start[NCLS + 2];             // segment starts per class
__device__ int   g_perm[QSZ];                   // permutation (sorted by label)
__device__ double g_acc[2];                     // [0]=cls nll sum, [1]=contrastive nll sum

// ---------------- row L2 normalize (block per row, 128 threads) -------------
__global__ void norm_rows(const float* __restrict__ x, float* __restrict__ y) {
    int r = blockIdx.x;
    const float4* xr = (const float4*)(x + (size_t)r * DIM);
    float4 v = xr[threadIdx.x];
    float ss = v.x * v.x + v.y * v.y + v.z * v.z + v.w * v.w;
#pragma unroll
    for (int o = 16; o; o >>= 1) ss += __shfl_down_sync(0xffffffffu, ss, o);
    __shared__ float sh[4];
    if ((threadIdx.x & 31) == 0) sh[threadIdx.x >> 5] = ss;
    __syncthreads();
    float tot = sh[0] + sh[1] + sh[2] + sh[3];
    float inv = 1.0f / fmaxf(sqrtf(tot), 1e-12f);
    float4 o4 = make_float4(v.x * inv, v.y * inv, v.z * inv, v.w * inv);
    ((float4*)(y + (size_t)r * DIM))[threadIdx.x] = o4;
}

// ---------------- counting sort of queue labels (single block) --------------
__global__ void build_perm(const int* __restrict__ labels) {
    __shared__ int cnt[NCLS + 1];
    __shared__ int cur[NCLS + 1];
    int tid = threadIdx.x;
    for (int i = tid; i < NCLS + 1; i += blockDim.x) cnt[i] = 0;
    if (tid == 0) { g_acc[0] = 0.0; g_acc[1] = 0.0; }
    __syncthreads();
    for (int q = tid; q < QSZ; q += blockDim.x) {
        int l = labels[q];
        int b = (l >= 0 && l < NCLS) ? l : NCLS;
        atomicAdd(&cnt[b], 1);
    }
    __syncthreads();
    if (tid == 0) {
        int run = 0;
        for (int c = 0; c < NCLS + 1; c++) {
            cur[c] = run;
            g_start[c] = run;
            run += cnt[c];
        }
        g_start[NCLS + 1] = run;
    }
    __syncthreads();
    for (int q = tid; q < QSZ; q += blockDim.x) {
        int l = labels[q];
        int b = (l >= 0 && l < NCLS) ? l : NCLS;
        int p = atomicAdd(&cur[b], 1);
        g_perm[p] = q;
    }
}

// ---------------- gather queue rows into label-sorted order -----------------
__global__ void permute_queue(const float* __restrict__ queue) {
    int idx = blockIdx.x * blockDim.x + threadIdx.x;  // QSZ * 128 threads
    int r = idx >> 7, c = idx & 127;
    int src = g_perm[r];
    ((float4*)g_qp)[(size_t)r * 128 + c] =
        ((const float4*)queue)[(size_t)src * 128 + c];
}

// ---------------- SGEMM: C[m,n] = alpha * sum_k A[m,k]*B[n,k] ---------------
// A: [M,K] row-major, Bm: [N,K] row-major, C: [M,N] row-major. M%128==0, K%8==0.
#define GBM 128
#define GBN 128
#define GBK 8
#define GTM 8
#define GTN 8
__global__ __launch_bounds__(256) void gemm_nt(const float* __restrict__ A,
                                               const float* __restrict__ Bm,
                                               float* __restrict__ Cm,
                                               int N, int K, float alpha) {
    __shared__ float As[GBK][GBM];
    __shared__ float Bs[GBK][GBN];
    int bx = blockIdx.x;  // N tile
    int by = blockIdx.y;  // M tile
    int tid = threadIdx.x;
    int lr = tid >> 1;            // 0..127 : row within tile for loading
    int lc = (tid & 1) * 4;       // 0 or 4 : k offset for float4 load
    int trow = (tid >> 4) * GTM;  // 0..120
    int tcol = (tid & 15) * GTN;  // 0..120

    float acc[GTM][GTN] = {};
    const float* Ap = A + (size_t)(by * GBM + lr) * K + lc;
    const float* Bp = Bm + (size_t)(bx * GBN + lr) * K + lc;
    bool bvalid = (bx * GBN + lr) < N;

    for (int k0 = 0; k0 < K; k0 += GBK) {
        float4 av = *(const float4*)(Ap + k0);
        As[lc + 0][lr] = av.x; As[lc + 1][lr] = av.y;
        As[lc + 2][lr] = av.z; As[lc + 3][lr] = av.w;
        float4 bv = make_float4(0.f, 0.f, 0.f, 0.f);
        if (bvalid) bv = *(const float4*)(Bp + k0);
        Bs[lc + 0][lr] = bv.x; Bs[lc + 1][lr] = bv.y;
        Bs[lc + 2][lr] = bv.z; Bs[lc + 3][lr] = bv.w;
        __syncthreads();
#pragma unroll
        for (int k = 0; k < GBK; k++) {
            float ar[GTM], br[GTN];
#pragma unroll
            for (int i = 0; i < GTM; i++) ar[i] = As[k][trow + i];
#pragma unroll
            for (int j = 0; j < GTN; j++) br[j] = Bs[k][tcol + j];
#pragma unroll
            for (int i = 0; i < GTM; i++)
#pragma unroll
                for (int j = 0; j < GTN; j++) acc[i][j] = fmaf(ar[i], br[j], acc[i][j]);
        }
        __syncthreads();
    }
#pragma unroll
    for (int i = 0; i < GTM; i++) {
        int gm = by * GBM + trow + i;
#pragma unroll
        for (int j = 0; j < GTN; j++) {
            int gn = bx * GBN + tcol + j;
            if (gn < N) Cm[(size_t)gm * N + gn] = alpha * acc[i][j];
        }
    }
}

// ---------------- contrastive CE: one block per batch row -------------------
__global__ __launch_bounds__(256) void row_contrastive(const float* __restrict__ prior,
                                                       const int* __restrict__ targets,
                                                       const unsigned char* __restrict__ init) {
    int b = blockIdx.x, tid = threadIdx.x;
    const float* Srow = g_S + (size_t)b * QSZ;
    const float* CSrow = g_CS + (size_t)b * NCLS;
    int tgt = targets[b];
    __shared__ float sm[256], ssum[256];
    __shared__ float stv;
    float m = -INFINITY, s = 0.f;
    for (int c = tid; c < NCLS; c += 256) {
        int s0 = g_start[c], s1 = g_start[c + 1];
        int cnt = s1 - s0;
        float ql = 0.f;
        if (cnt > 0) {
            float mx = -INFINITY;
            for (int q = s0; q < s1; q++) mx = fmaxf(mx, Srow[q]);
            float se = 0.f;
            for (int q = s0; q < s1; q++) se += __expf(Srow[q] - mx);
            ql = mx + __logf(se) - __logf((float)cnt);
        }
        float cl = init[c] ? CSrow[c] : 0.f;
        float a = fmaxf(cl, ql), d = fminf(cl, ql);
        float comp = a + log1pf(__expf(d - a));            // logaddexp
        float v = comp - logf(fmaxf(prior[c], EPSP));      // - prior_adjust
        if (c == tgt) stv = v;
        if (v > m) { s = s * __expf(m - v) + 1.f; m = v; }
        else        { s += __expf(v - m); }
    }
    sm[tid] = m; ssum[tid] = s;
    __syncthreads();
    for (int o = 128; o; o >>= 1) {
        if (tid < o) {
            float m2 = sm[tid + o], s2 = ssum[tid + o];
            float M = fmaxf(sm[tid], m2);
            ssum[tid] = ssum[tid] * __expf(sm[tid] - M) + s2 * __expf(m2 - M);
            sm[tid] = M;
        }
        __syncthreads();
    }
    if (tid == 0) {
        float lse = sm[0] + __logf(ssum[0]);
        atomicAdd(&g_acc[1], (double)(lse - stv));
    }
}

// ---------------- plain classification CE: one block per batch row ----------
__global__ __launch_bounds__(256) void row_cls(const float* __restrict__ logits,
                                               const float* __restrict__ prior,
                                               const int* __restrict__ targets) {
    int b = blockIdx.x, tid = threadIdx.x;
    const float* L = logits + (size_t)b * NCLS;
    int tgt = targets[b];
    __shared__ float sm[256], ssum[256];
    __shared__ float stv;
    float m = -INFINITY, s = 0.f;
    for (int c = tid; c < NCLS; c += 256) {
        float v = L[c] - logf(fmaxf(prior[c], EPSP));
        if (c == tgt) stv = v;
        if (v > m) { s = s * __expf(m - v) + 1.f; m = v; }
        else        { s += __expf(v - m); }
    }
    sm[tid] = m; ssum[tid] = s;
    __syncthreads();
    for (int o = 128; o; o >>= 1) {
        if (tid < o) {
            float m2 = sm[tid + o], s2 = ssum[tid + o];
            float M = fmaxf(sm[tid], m2);
            ssum[tid] = ssum[tid] * __expf(sm[tid] - M) + s2 * __expf(m2 - M);
            sm[tid] = M;
        }
        __syncthreads();
    }
    if (tid == 0) {
        float lse = sm[0] + __logf(ssum[0]);
        atomicAdd(&g_acc[0], (double)(lse - stv));
    }
}

__global__ void finalize(float* out) {
    out[0] = (float)(1.0 * (g_acc[0] / BATCH) + 0.1 * (g_acc[1] / BATCH));
}

// ---------------- launch ----------------------------------------------------
extern "C" void kernel_launch(void* const* d_in, const int* in_sizes, int n_in,
                              void* d_out, int out_size) {
    const float* logits    = (const float*)d_in[0];          // [4096,1000]
    const float* embed     = (const float*)d_in[1];          // [4096,512]
    const float* centers   = (const float*)d_in[2];          // [1000,512]
    const float* queue     = (const float*)d_in[3];          // [8192,512]
    const float* prior     = (const float*)d_in[4];          // [1000]
    const int*   targets   = (const int*)d_in[5];            // [4096]
    const unsigned char* cinit = (const unsigned char*)d_in[6]; // [1000] bool
    const int*   qlabels   = (const int*)d_in[7];            // [8192]
    float* out = (float*)d_out;

    float* feat; cudaGetSymbolAddress((void**)&feat, g_feat);
    float* cent; cudaGetSymbolAddress((void**)&cent, g_cent);
    float* qp;   cudaGetSymbolAddress((void**)&qp,   g_qp);
    float* S;    cudaGetSymbolAddress((void**)&S,    g_S);
    float* CS;   cudaGetSymbolAddress((void**)&CS,   g_CS);

    norm_rows<<<BATCH, 128>>>(embed, feat);
    norm_rows<<<NCLS, 128>>>(centers, cent);
    build_perm<<<1, 1024>>>(qlabels);
    permute_queue<<<(QSZ * 128) / 256, 256>>>(queue);

    dim3 gS(QSZ / GBN, BATCH / GBM);
    gemm_nt<<<gS, 256>>>(feat, qp, S, QSZ, DIM, INV_T);
    dim3 gC((NCLS + GBN - 1) / GBN, BATCH / GBM);
    gemm_nt<<<gC, 256>>>(feat, cent, CS, NCLS, DIM, INV_T);

    row_contrastive<<<BATCH, 256>>>(prior, targets, cinit);
    row_cls<<<BATCH, 256>>>(logits, prior, targets);
    finalize<<<1, 1>>>(out);
}